// round 4
// baseline (speedup 1.0000x reference)
#include <cuda_runtime.h>

#define NPTS    8192
#define BATCH   8
#define NPOINT  512
#define NSAMPLE 32
#define NT      (BATCH*NPOINT*NSAMPLE)   // 131072 samples
#define NSTILE  512                      // sample tiles of 256 in layer kernels

// ---------------- scratch (device globals; no allocation) ----------------
__device__ float g_X0[67u*NT];    // layer0 input features [c][t]
__device__ float g_Y0[64u*NT];    // layer0 raw output (pre-BN)
__device__ float g_Y1[64u*NT];    // layer1 raw output
__device__ float g_Y2[128u*NT];   // layer2 raw output
__device__ float g_newxyz[BATCH*NPOINT*3];   // (b,s,3) centroids
__device__ float g_psum[128*NSTILE];
__device__ float g_psq [128*NSTILE];
__device__ float g_scale[128];
__device__ float g_shift[128];

// ---------------- packed f32x2 helpers (per-half rounding == scalar ops) ---
typedef unsigned long long u64;
__device__ __forceinline__ u64 pk2(float lo, float hi) {
    u64 r; asm("mov.b64 %0,{%1,%2};" : "=l"(r) : "f"(lo), "f"(hi)); return r;
}
__device__ __forceinline__ void upk2(u64 v, float& lo, float& hi) {
    asm("mov.b64 {%0,%1},%2;" : "=f"(lo), "=f"(hi) : "l"(v));
}
__device__ __forceinline__ u64 add2(u64 a, u64 b) {
    u64 r; asm("add.rn.f32x2 %0,%1,%2;" : "=l"(r) : "l"(a), "l"(b)); return r;
}
__device__ __forceinline__ u64 mul2(u64 a, u64 b) {
    u64 r; asm("mul.rn.f32x2 %0,%1,%2;" : "=l"(r) : "l"(a), "l"(b)); return r;
}
__device__ __forceinline__ u64 fma2(u64 a, u64 b, u64 c) {
    u64 r; asm("fma.rn.f32x2 %0,%1,%2,%3;" : "=l"(r) : "l"(a), "l"(b), "l"(c)); return r;
}

// ---------------- FPS ----------------
// One CTA per batch, 1024 threads, 8 points/thread in registers (packed f32x2,
// 24 regs) + dist[8]. Distance arithmetic is the bit-exact verified formula:
// per half, dx=rn(px-cx); d=fma(dz,dz,fma(dy,dy,rn(dx*dx))); dist=min(dist,d).
// Argmax: exact-value max (nonneg floats -> u32 bits monotone) via REDUX,
// first-index tie-break via REDUX-min on candidate indices.
__global__ __launch_bounds__(1024) void fps_kernel(const float* __restrict__ xyz,
                                                   float* __restrict__ out_newxyz)
{
    const int b    = blockIdx.x;
    const int tid  = threadIdx.x;
    const int lane = tid & 31;
    const int w    = tid >> 5;
    const float* X = xyz + (size_t)b * 3 * NPTS;

    u64 px2[4], py2[4], pz2[4];
    float dist[8];
    #pragma unroll
    for (int m = 0; m < 4; m++) {
        int i0 = tid + (2 * m) * 1024;
        px2[m] = pk2(X[i0],            X[i0 + 1024]);
        py2[m] = pk2(X[i0 + NPTS],     X[i0 + 1024 + NPTS]);
        pz2[m] = pk2(X[i0 + 2*NPTS],   X[i0 + 1024 + 2*NPTS]);
        dist[2 * m] = 1e10f; dist[2 * m + 1] = 1e10f;
    }

    __shared__ float    s_v[2][32];
    __shared__ unsigned s_i[2][32];

    // ---- init: far = argmax over x (first-index ties). x >= 0 always. ----
    unsigned far;
    {
        float lv = -1.0f; unsigned li = 0xffffffffu;
        #pragma unroll
        for (int m = 3; m >= 0; m--) {
            float x0, x1; upk2(px2[m], x0, x1);
            if (x1 >= lv) { lv = x1; li = tid + (2 * m + 1) * 1024; }
            if (x0 >= lv) { lv = x0; li = tid + (2 * m) * 1024; }
        }
        unsigned wmax = __reduce_max_sync(0xffffffffu, __float_as_uint(lv));
        unsigned cand = (__float_as_uint(lv) == wmax) ? li : 0xffffffffu;
        unsigned wmin = __reduce_min_sync(0xffffffffu, cand);
        if (lane == 0) { s_v[1][w] = __uint_as_float(wmax); s_i[1][w] = wmin; }
        __syncthreads();
        float    v2 = s_v[1][lane];
        unsigned i2 = s_i[1][lane];
        unsigned bmax = __reduce_max_sync(0xffffffffu, __float_as_uint(v2));
        unsigned c2   = (__float_as_uint(v2) == bmax) ? i2 : 0xffffffffu;
        far = __reduce_min_sync(0xffffffffu, c2);
    }

    for (int s = 0; s < NPOINT; s++) {
        const float cx = X[far];
        const float cy = X[far + NPTS];
        const float cz = X[far + 2 * NPTS];
        if (tid == 0) {
            out_newxyz[(b * 3 + 0) * NPOINT + s] = cx;
            out_newxyz[(b * 3 + 1) * NPOINT + s] = cy;
            out_newxyz[(b * 3 + 2) * NPOINT + s] = cz;
            g_newxyz[(b * NPOINT + s) * 3 + 0] = cx;
            g_newxyz[(b * NPOINT + s) * 3 + 1] = cy;
            g_newxyz[(b * NPOINT + s) * 3 + 2] = cz;
        }
        const u64 ncx2 = pk2(-cx, -cx);
        const u64 ncy2 = pk2(-cy, -cy);
        const u64 ncz2 = pk2(-cz, -cz);
        #pragma unroll
        for (int m = 0; m < 4; m++) {
            u64 dx2 = add2(px2[m], ncx2);
            u64 dy2 = add2(py2[m], ncy2);
            u64 dz2 = add2(pz2[m], ncz2);
            u64 d2  = fma2(dz2, dz2, fma2(dy2, dy2, mul2(dx2, dx2)));
            float d0, d1; upk2(d2, d0, d1);
            dist[2 * m]     = fminf(dist[2 * m],     d0);
            dist[2 * m + 1] = fminf(dist[2 * m + 1], d1);
        }
        // local max value (tree) then first matching index (descending j)
        float lv = fmaxf(fmaxf(fmaxf(dist[0], dist[1]), fmaxf(dist[2], dist[3])),
                         fmaxf(fmaxf(dist[4], dist[5]), fmaxf(dist[6], dist[7])));
        unsigned li = 0xffffffffu;
        #pragma unroll
        for (int j = 7; j >= 0; j--)
            if (dist[j] == lv) li = tid + j * 1024;

        unsigned wmax = __reduce_max_sync(0xffffffffu, __float_as_uint(lv));
        unsigned cand = (__float_as_uint(lv) == wmax) ? li : 0xffffffffu;
        unsigned wmin = __reduce_min_sync(0xffffffffu, cand);
        const int p = s & 1;
        if (lane == 0) { s_v[p][w] = __uint_as_float(wmax); s_i[p][w] = wmin; }
        __syncthreads();
        float    v2 = s_v[p][lane];
        unsigned i2 = s_i[p][lane];
        unsigned bmax = __reduce_max_sync(0xffffffffu, __float_as_uint(v2));
        unsigned c2   = (__float_as_uint(v2) == bmax) ? i2 : 0xffffffffu;
        far = __reduce_min_sync(0xffffffffu, c2);
    }
}

// ---------------- ball query + gather (one warp per (b,s)) ----------------
// Distance rounds EXACTLY like the reference (verified):
//   dot  = fma(c2,p2, fma(c1,p1, rn(c0*p0)))
//   |v|^2 = rn(rn(x*x + y*y) + z*z)  built from plain mul/add (NO fma)
//   d    = rn(rn(-2*dot + |src|^2) + |dst|^2)
__global__ __launch_bounds__(256) void ball_gather_kernel(const float* __restrict__ xyz,
                                                          const float* __restrict__ points)
{
    const int w    = blockIdx.x * 8 + (threadIdx.x >> 5);
    const int lane = threadIdx.x & 31;
    const int b = w >> 9;
    const int s = w & 511;

    const float* X  = xyz + (size_t)b * 3 * NPTS;
    const float* Yc = X + NPTS;
    const float* Z  = X + 2 * NPTS;

    const float cx = g_newxyz[(b * NPOINT + s) * 3 + 0];
    const float cy = g_newxyz[(b * NPOINT + s) * 3 + 1];
    const float cz = g_newxyz[(b * NPOINT + s) * 3 + 2];
    const float cc = __fadd_rn(__fadd_rn(__fmul_rn(cx, cx), __fmul_rn(cy, cy)),
                               __fmul_rn(cz, cz));
    const float r2 = 0.04f;

    __shared__ int nbr_s[8][NSAMPLE];
    int* nbr = nbr_s[threadIdx.x >> 5];

    int found = 0;
    for (int base = 0; base < NPTS; base += 32) {
        int   j  = base + lane;
        float xj = X[j], yj = Yc[j], zj = Z[j];
        float dot = fmaf(cz, zj, fmaf(cy, yj, __fmul_rn(cx, xj)));
        float pp  = __fadd_rn(__fadd_rn(__fmul_rn(xj, xj), __fmul_rn(yj, yj)),
                              __fmul_rn(zj, zj));
        float d   = __fadd_rn(__fadd_rn(__fmul_rn(-2.0f, dot), cc), pp);
        bool in   = !(d > r2);
        unsigned m = __ballot_sync(0xffffffffu, in);
        int pos = found + __popc(m & ((1u << lane) - 1u));
        if (in && pos < NSAMPLE) nbr[pos] = j;
        found += __popc(m);
        if (found >= NSAMPLE) break;
    }
    __syncwarp();
    if (found > NSAMPLE) found = NSAMPLE;
    int j0 = nbr[0];
    int j  = (lane < found) ? nbr[lane] : j0;

    const int t = (b * NPOINT + s) * NSAMPLE + lane;
    g_X0[0u * NT + t] = X[j]  - cx;
    g_X0[1u * NT + t] = Yc[j] - cy;
    g_X0[2u * NT + t] = Z[j]  - cz;
    const float* P = points + (size_t)b * 64 * NPTS;
    #pragma unroll 4
    for (int d = 0; d < 64; d++) {
        g_X0[(size_t)(3 + d) * NT + t] = P[(size_t)d * NPTS + j];
    }
}

// ---------------- fused layer GEMM, 8x8 register blocked, fused BN stats ---
// Block = 256 threads (tx=lane 0..31, warp wp=0..7). Tile = 256 samples x 64
// outputs. Thread computes 8 samples (tx + 32k) x 8 outputs (wp*8+j).
// Weights staged TRANSPOSED (WsT[c][o]) so the 8 per-cc weights are fetched
// as 2 broadcast LDS.128. Input BN+ReLU applied once at X staging. Epilogue
// emits per-block per-channel sum/sumsq partials (deterministic, no atomics).
#define CCH 16
template<int CIN, bool BNIN, int LAYER>
__global__ __launch_bounds__(256, 2) void layer_kernel(const float* __restrict__ W,
                                                       const float* __restrict__ bias)
{
    const float* Xin  = (LAYER == 0) ? g_X0 : (LAYER == 1) ? g_Y0 : g_Y1;
    float*       Yout = (LAYER == 0) ? g_Y0 : (LAYER == 1) ? g_Y1 : g_Y2;

    __shared__ __align__(16) float WsT[CIN * 64];   // [c][o]
    __shared__ float bs2[64];
    __shared__ float Xs[CCH * 256];
    __shared__ float sc[CIN];
    __shared__ float sh[CIN];

    const int tid   = threadIdx.x;
    const int tx    = tid & 31;
    const int wp    = tid >> 5;
    const int obase = blockIdx.y * 64;
    const int tbase = blockIdx.x * 256;

    // transpose-stage W: i -> (o = i & 63, c = i >> 6); STS conflict-free.
    const float* Wg = W + (size_t)obase * CIN;
    for (int i = tid; i < 64 * CIN; i += 256) {
        int o = i & 63, c = i >> 6;
        WsT[c * 64 + o] = Wg[o * CIN + c];
    }
    for (int i = tid; i < 64; i += 256) bs2[i] = bias[obase + i];
    if (BNIN) {
        for (int i = tid; i < CIN; i += 256) { sc[i] = g_scale[i]; sh[i] = g_shift[i]; }
    }
    __syncthreads();

    float acc[8][8];
    {
        float b0[8];
        #pragma unroll
        for (int j = 0; j < 8; j++) b0[j] = bs2[wp * 8 + j];
        #pragma unroll
        for (int k = 0; k < 8; k++)
            #pragma unroll
            for (int j = 0; j < 8; j++) acc[k][j] = b0[j];
    }

    for (int c0 = 0; c0 < CIN; c0 += CCH) {
        const int cn = (CIN - c0 < CCH) ? (CIN - c0) : CCH;
        __syncthreads();
        for (int e = tid; e < cn * 64; e += 256) {
            int cc   = e >> 6;
            int col4 = (e & 63) << 2;
            float4 v = *reinterpret_cast<const float4*>(
                Xin + (size_t)(c0 + cc) * NT + tbase + col4);
            if (BNIN) {
                float s = sc[c0 + cc], h = sh[c0 + cc];
                v.x = fmaxf(0.f, fmaf(v.x, s, h));
                v.y = fmaxf(0.f, fmaf(v.y, s, h));
                v.z = fmaxf(0.f, fmaf(v.z, s, h));
                v.w = fmaxf(0.f, fmaf(v.w, s, h));
            }
            *reinterpret_cast<float4*>(Xs + cc * 256 + col4) = v;
        }
        __syncthreads();
        for (int cc = 0; cc < cn; cc++) {
            float xv[8];
            #pragma unroll
            for (int k = 0; k < 8; k++) xv[k] = Xs[cc * 256 + tx + 32 * k];
            float4 wA = *reinterpret_cast<const float4*>(&WsT[(c0 + cc) * 64 + wp * 8]);
            float4 wB = *reinterpret_cast<const float4*>(&WsT[(c0 + cc) * 64 + wp * 8 + 4]);
            float wv[8] = {wA.x, wA.y, wA.z, wA.w, wB.x, wB.y, wB.z, wB.w};
            #pragma unroll
            for (int j = 0; j < 8; j++)
                #pragma unroll
                for (int k = 0; k < 8; k++)
                    acc[k][j] = fmaf(wv[j], xv[k], acc[k][j]);
        }
    }

    // write Y (coalesced per (j,k): lanes consecutive over tx)
    #pragma unroll
    for (int j = 0; j < 8; j++) {
        const int o = obase + wp * 8 + j;
        float* yp = Yout + (size_t)o * NT + tbase + tx;
        #pragma unroll
        for (int k = 0; k < 8; k++) yp[32 * k] = acc[k][j];
    }

    // fused per-channel partial stats for this block's 256 samples
    #pragma unroll
    for (int j = 0; j < 8; j++) {
        float s = 0.f, q = 0.f;
        #pragma unroll
        for (int k = 0; k < 8; k++) {
            float v = acc[k][j];
            s += v;
            q = fmaf(v, v, q);
        }
        #pragma unroll
        for (int off = 16; off; off >>= 1) {
            s += __shfl_down_sync(0xffffffffu, s, off);
            q += __shfl_down_sync(0xffffffffu, q, off);
        }
        if (tx == 0) {
            const int o = obase + wp * 8 + j;
            g_psum[o * NSTILE + blockIdx.x] = s;
            g_psq [o * NSTILE + blockIdx.x] = q;
        }
    }
}

// ---------------- reduce partials -> BN scale/shift (layers 0,1) ----------
__global__ __launch_bounds__(256) void finalize_kernel(const float* __restrict__ g,
                                                       const float* __restrict__ beta)
{
    const int c = blockIdx.x;
    float s = 0.f, q = 0.f;
    for (int i = threadIdx.x; i < NSTILE; i += 256) {
        s += g_psum[c * NSTILE + i];
        q += g_psq [c * NSTILE + i];
    }
    __shared__ float rs[8], rq[8];
    #pragma unroll
    for (int off = 16; off; off >>= 1) {
        s += __shfl_down_sync(0xffffffffu, s, off);
        q += __shfl_down_sync(0xffffffffu, q, off);
    }
    int w = threadIdx.x >> 5;
    if ((threadIdx.x & 31) == 0) { rs[w] = s; rq[w] = q; }
    __syncthreads();
    if (threadIdx.x == 0) {
        float ts = 0.f, tq = 0.f;
        #pragma unroll
        for (int i = 0; i < 8; i++) { ts += rs[i]; tq += rq[i]; }
        float mu  = ts * (1.0f / NT);
        float var = tq * (1.0f / NT) - mu * mu;
        float rsq = rsqrtf(var + 1e-5f);
        float scv = g[c] * rsq;
        g_scale[c] = scv;
        g_shift[c] = fmaf(-mu, scv, beta[c]);
    }
}

// ---------------- layer-2 BN finalize + BN + ReLU + max over k ------------
// one block per (b, o); derives channel-o scale/shift from partials inline.
__global__ __launch_bounds__(256) void final_kernel(float* __restrict__ out2,
                                                    const float* __restrict__ g,
                                                    const float* __restrict__ beta)
{
    const int bo = blockIdx.x;
    const int b = bo >> 7;
    const int o = bo & 127;
    const int tid  = threadIdx.x;
    const int w    = tid >> 5;
    const int lane = tid & 31;

    __shared__ float rs[8], rq[8];
    __shared__ float s_sc, s_sh;
    {
        float s = 0.f, q = 0.f;
        for (int i = tid; i < NSTILE; i += 256) {
            s += g_psum[o * NSTILE + i];
            q += g_psq [o * NSTILE + i];
        }
        #pragma unroll
        for (int off = 16; off; off >>= 1) {
            s += __shfl_down_sync(0xffffffffu, s, off);
            q += __shfl_down_sync(0xffffffffu, q, off);
        }
        if (lane == 0) { rs[w] = s; rq[w] = q; }
        __syncthreads();
        if (tid == 0) {
            float ts = 0.f, tq = 0.f;
            #pragma unroll
            for (int i = 0; i < 8; i++) { ts += rs[i]; tq += rq[i]; }
            float mu  = ts * (1.0f / NT);
            float var = tq * (1.0f / NT) - mu * mu;
            float rsq = rsqrtf(var + 1e-5f);
            float scv = g[o] * rsq;
            s_sc = scv;
            s_sh = fmaf(-mu, scv, beta[o]);
        }
        __syncthreads();
    }
    const float scv = s_sc;
    const float shv = s_sh;

    const float* p = g_Y2 + (size_t)o * NT + (size_t)b * (NPOINT * NSAMPLE);
    for (int r = 0; r < 64; r++) {
        float v = p[tid + r * 256];
        v = fmaxf(0.f, fmaf(v, scv, shv));
        #pragma unroll
        for (int off = 16; off; off >>= 1)
            v = fmaxf(v, __shfl_down_sync(0xffffffffu, v, off));
        if (lane == 0)
            out2[(b * 128 + o) * NPOINT + (w + 8 * r)] = v;
    }
}

// ---------------- launch ----------------
extern "C" void kernel_launch(void* const* d_in, const int* in_sizes, int n_in,
                              void* d_out, int out_size)
{
    (void)in_sizes; (void)n_in; (void)out_size;
    const float* xyz    = (const float*)d_in[0];
    const float* points = (const float*)d_in[1];
    const float* W0 = (const float*)d_in[2];
    const float* b0 = (const float*)d_in[3];
    const float* g0 = (const float*)d_in[4];
    const float* be0= (const float*)d_in[5];
    const float* W1 = (const float*)d_in[6];
    const float* b1 = (const float*)d_in[7];
    const float* g1 = (const float*)d_in[8];
    const float* be1= (const float*)d_in[9];
    const float* W2 = (const float*)d_in[10];
    const float* b2 = (const float*)d_in[11];
    const float* g2 = (const float*)d_in[12];
    const float* be2= (const float*)d_in[13];

    float* out = (float*)d_out;

    fps_kernel<<<BATCH, 1024>>>(xyz, out);
    ball_gather_kernel<<<(BATCH * NPOINT) / 8, 256>>>(xyz, points);

    layer_kernel<67, false, 0><<<dim3(NSTILE, 1), 256>>>(W0, b0);
    finalize_kernel<<<64, 256>>>(g0, be0);

    layer_kernel<64, true, 1><<<dim3(NSTILE, 1), 256>>>(W1, b1);
    finalize_kernel<<<64, 256>>>(g1, be1);

    layer_kernel<64, true, 2><<<dim3(NSTILE, 2), 256>>>(W2, b2);

    final_kernel<<<BATCH * 128, 256>>>(out + BATCH * 3 * NPOINT, g2, be2);
}

// round 5
// speedup vs baseline: 1.3238x; 1.3238x over previous
#include <cuda_runtime.h>

#define NPTS    8192
#define BATCH   8
#define NPOINT  512
#define NSAMPLE 32
#define NT      (BATCH*NPOINT*NSAMPLE)   // 131072 samples
#define NSTILE  512                      // sample tiles of 256 in layer kernels

// ---------------- scratch (device globals; no allocation) ----------------
__device__ float g_X0[67u*NT];    // layer0 input features [c][t]
__device__ float g_Y0[64u*NT];    // layer0 raw output (pre-BN)
__device__ float g_Y1[64u*NT];    // layer1 raw output
__device__ float g_Y2[128u*NT];   // layer2 raw output
__device__ float g_newxyz[BATCH*NPOINT*3];   // (b,s,3) centroids
__device__ float g_psum[128*NSTILE];
__device__ float g_psq [128*NSTILE];
__device__ float g_scale[128];
__device__ float g_shift[128];

// ---------------- packed f32x2 helpers (per-half rounding == scalar ops) ---
typedef unsigned long long u64;
__device__ __forceinline__ u64 pk2(float lo, float hi) {
    u64 r; asm("mov.b64 %0,{%1,%2};" : "=l"(r) : "f"(lo), "f"(hi)); return r;
}
__device__ __forceinline__ void upk2(u64 v, float& lo, float& hi) {
    asm("mov.b64 {%0,%1},%2;" : "=f"(lo), "=f"(hi) : "l"(v));
}
__device__ __forceinline__ u64 add2(u64 a, u64 b) {
    u64 r; asm("add.rn.f32x2 %0,%1,%2;" : "=l"(r) : "l"(a), "l"(b)); return r;
}
__device__ __forceinline__ u64 mul2(u64 a, u64 b) {
    u64 r; asm("mul.rn.f32x2 %0,%1,%2;" : "=l"(r) : "l"(a), "l"(b)); return r;
}
__device__ __forceinline__ u64 fma2(u64 a, u64 b, u64 c) {
    u64 r; asm("fma.rn.f32x2 %0,%1,%2,%3;" : "=l"(r) : "l"(a), "l"(b), "l"(c)); return r;
}

// ---------------- FPS ----------------
// REVERTED to the round-2 kernel that measured 797us total (REDUX variant
// regressed badly: 4 atom-unit collectives/warp/iter serialize across 32
// warps). One CTA per batch, 1024 threads, 8 pts/thread in packed f32x2
// registers. Arithmetic bit-exact vs reference (verified round 1/2).
__device__ __forceinline__ void warp_argmax(float& v, int& i) {
    #pragma unroll
    for (int off = 16; off; off >>= 1) {
        float v2 = __shfl_down_sync(0xffffffffu, v, off);
        int   i2 = __shfl_down_sync(0xffffffffu, i, off);
        if (v2 > v || (v2 == v && i2 < i)) { v = v2; i = i2; }
    }
}

__global__ __launch_bounds__(1024) void fps_kernel(const float* __restrict__ xyz,
                                                   float* __restrict__ out_newxyz)
{
    const int b   = blockIdx.x;
    const int tid = threadIdx.x;
    const float* X  = xyz + (size_t)b * 3 * NPTS;
    const float* Yc = X + NPTS;
    const float* Z  = X + 2 * NPTS;

    // pack pairs (j=2m, j=2m+1): lo index tid+2m*1024, hi index tid+(2m+1)*1024
    u64 px2[4], py2[4], pz2[4];
    float dist[8];
    float pxs[8];
    #pragma unroll
    for (int j = 0; j < 8; j++) {
        int i = tid + j * 1024;
        pxs[j] = X[i];
        dist[j] = 1e10f;
    }
    #pragma unroll
    for (int m = 0; m < 4; m++) {
        int i0 = tid + (2 * m) * 1024, i1 = i0 + 1024;
        px2[m] = pk2(pxs[2 * m], pxs[2 * m + 1]);
        py2[m] = pk2(Yc[i0], Yc[i1]);
        pz2[m] = pk2(Z[i0],  Z[i1]);
    }

    __shared__ float s_v[32];
    __shared__ int   s_i[32];
    __shared__ int   s_far;

    // initial far = argmax of x coordinate (first-index ties)
    float bv = -1e30f; int bi = 0;
    #pragma unroll
    for (int j = 0; j < 8; j++) {
        int i = tid + j * 1024;
        if (pxs[j] > bv) { bv = pxs[j]; bi = i; }
    }
    {
        warp_argmax(bv, bi);
        int w = tid >> 5;
        if ((tid & 31) == 0) { s_v[w] = bv; s_i[w] = bi; }
        __syncthreads();
        if (w == 0) {
            float v = s_v[tid]; int i = s_i[tid];
            warp_argmax(v, i);
            if (tid == 0) s_far = i;
        }
        __syncthreads();
    }
    int far = s_far;

    for (int s = 0; s < NPOINT; s++) {
        float cx = X[far], cy = Yc[far], cz = Z[far];
        if (tid == 0) {
            out_newxyz[(b * 3 + 0) * NPOINT + s] = cx;
            out_newxyz[(b * 3 + 1) * NPOINT + s] = cy;
            out_newxyz[(b * 3 + 2) * NPOINT + s] = cz;
            g_newxyz[(b * NPOINT + s) * 3 + 0] = cx;
            g_newxyz[(b * NPOINT + s) * 3 + 1] = cy;
            g_newxyz[(b * NPOINT + s) * 3 + 2] = cz;
        }
        const u64 ncx2 = pk2(-cx, -cx);
        const u64 ncy2 = pk2(-cy, -cy);
        const u64 ncz2 = pk2(-cz, -cz);
        float lv = -1e30f; int li = 0;
        #pragma unroll
        for (int m = 0; m < 4; m++) {
            u64 dx2 = add2(px2[m], ncx2);          // rn(px - cx) per half
            u64 dy2 = add2(py2[m], ncy2);
            u64 dz2 = add2(pz2[m], ncz2);
            u64 d2  = fma2(dz2, dz2, fma2(dy2, dy2, mul2(dx2, dx2)));
            float d0, d1; upk2(d2, d0, d1);
            float nd0 = fminf(dist[2 * m], d0);     dist[2 * m]     = nd0;
            if (nd0 > lv) { lv = nd0; li = tid + (2 * m) * 1024; }
            float nd1 = fminf(dist[2 * m + 1], d1); dist[2 * m + 1] = nd1;
            if (nd1 > lv) { lv = nd1; li = tid + (2 * m + 1) * 1024; }
        }
        warp_argmax(lv, li);
        int w = tid >> 5;
        if ((tid & 31) == 0) { s_v[w] = lv; s_i[w] = li; }
        __syncthreads();
        if (w == 0) {
            float v = s_v[tid]; int i = s_i[tid];
            warp_argmax(v, i);
            if (tid == 0) s_far = i;
        }
        __syncthreads();
        far = s_far;
    }
}

// ---------------- ball query + gather (one warp per (b,s)) ----------------
// Distance rounds EXACTLY like the reference (verified):
//   dot  = fma(c2,p2, fma(c1,p1, rn(c0*p0)))
//   |v|^2 = rn(rn(x*x + y*y) + z*z)  built from plain mul/add (NO fma)
//   d    = rn(rn(-2*dot + |src|^2) + |dst|^2)
__global__ __launch_bounds__(256) void ball_gather_kernel(const float* __restrict__ xyz,
                                                          const float* __restrict__ points)
{
    const int w    = blockIdx.x * 8 + (threadIdx.x >> 5);
    const int lane = threadIdx.x & 31;
    const int b = w >> 9;
    const int s = w & 511;

    const float* X  = xyz + (size_t)b * 3 * NPTS;
    const float* Yc = X + NPTS;
    const float* Z  = X + 2 * NPTS;

    const float cx = g_newxyz[(b * NPOINT + s) * 3 + 0];
    const float cy = g_newxyz[(b * NPOINT + s) * 3 + 1];
    const float cz = g_newxyz[(b * NPOINT + s) * 3 + 2];
    const float cc = __fadd_rn(__fadd_rn(__fmul_rn(cx, cx), __fmul_rn(cy, cy)),
                               __fmul_rn(cz, cz));
    const float r2 = 0.04f;

    __shared__ int nbr_s[8][NSAMPLE];
    int* nbr = nbr_s[threadIdx.x >> 5];

    int found = 0;
    for (int base = 0; base < NPTS; base += 32) {
        int   j  = base + lane;
        float xj = X[j], yj = Yc[j], zj = Z[j];
        float dot = fmaf(cz, zj, fmaf(cy, yj, __fmul_rn(cx, xj)));
        float pp  = __fadd_rn(__fadd_rn(__fmul_rn(xj, xj), __fmul_rn(yj, yj)),
                              __fmul_rn(zj, zj));
        float d   = __fadd_rn(__fadd_rn(__fmul_rn(-2.0f, dot), cc), pp);
        bool in   = !(d > r2);
        unsigned m = __ballot_sync(0xffffffffu, in);
        int pos = found + __popc(m & ((1u << lane) - 1u));
        if (in && pos < NSAMPLE) nbr[pos] = j;
        found += __popc(m);
        if (found >= NSAMPLE) break;
    }
    __syncwarp();
    if (found > NSAMPLE) found = NSAMPLE;
    int j0 = nbr[0];
    int j  = (lane < found) ? nbr[lane] : j0;

    const int t = (b * NPOINT + s) * NSAMPLE + lane;
    g_X0[0u * NT + t] = X[j]  - cx;
    g_X0[1u * NT + t] = Yc[j] - cy;
    g_X0[2u * NT + t] = Z[j]  - cz;
    const float* P = points + (size_t)b * 64 * NPTS;
    #pragma unroll 4
    for (int d = 0; d < 64; d++) {
        g_X0[(size_t)(3 + d) * NT + t] = P[(size_t)d * NPTS + j];
    }
}

// ---------------- fused layer GEMM, 8x8 register blocked, fused BN stats ---
// Block = 256 threads (tx=lane 0..31, warp wp=0..7). Tile = 256 samples x 64
// outputs. Thread computes 8 samples (tx + 32k) x 8 outputs (wp*8+j).
// Weights staged TRANSPOSED (WsT[c][o]) so the 8 per-cc weights are fetched
// as 2 broadcast LDS.128. Input BN+ReLU applied once at X staging. Epilogue
// emits per-block per-channel sum/sumsq partials (deterministic, no atomics).
#define CCH 16
template<int CIN, bool BNIN, int LAYER>
__global__ __launch_bounds__(256, 2) void layer_kernel(const float* __restrict__ W,
                                                       const float* __restrict__ bias)
{
    const float* Xin  = (LAYER == 0) ? g_X0 : (LAYER == 1) ? g_Y0 : g_Y1;
    float*       Yout = (LAYER == 0) ? g_Y0 : (LAYER == 1) ? g_Y1 : g_Y2;

    __shared__ __align__(16) float WsT[CIN * 64];   // [c][o]
    __shared__ float bs2[64];
    __shared__ float Xs[CCH * 256];
    __shared__ float sc[CIN];
    __shared__ float sh[CIN];

    const int tid   = threadIdx.x;
    const int tx    = tid & 31;
    const int wp    = tid >> 5;
    const int obase = blockIdx.y * 64;
    const int tbase = blockIdx.x * 256;

    // transpose-stage W: i -> (o = i & 63, c = i >> 6); STS conflict-free.
    const float* Wg = W + (size_t)obase * CIN;
    for (int i = tid; i < 64 * CIN; i += 256) {
        int o = i & 63, c = i >> 6;
        WsT[c * 64 + o] = Wg[o * CIN + c];
    }
    for (int i = tid; i < 64; i += 256) bs2[i] = bias[obase + i];
    if (BNIN) {
        for (int i = tid; i < CIN; i += 256) { sc[i] = g_scale[i]; sh[i] = g_shift[i]; }
    }
    __syncthreads();

    float acc[8][8];
    {
        float b0[8];
        #pragma unroll
        for (int j = 0; j < 8; j++) b0[j] = bs2[wp * 8 + j];
        #pragma unroll
        for (int k = 0; k < 8; k++)
            #pragma unroll
            for (int j = 0; j < 8; j++) acc[k][j] = b0[j];
    }

    for (int c0 = 0; c0 < CIN; c0 += CCH) {
        const int cn = (CIN - c0 < CCH) ? (CIN - c0) : CCH;
        __syncthreads();
        for (int e = tid; e < cn * 64; e += 256) {
            int cc   = e >> 6;
            int col4 = (e & 63) << 2;
            float4 v = *reinterpret_cast<const float4*>(
                Xin + (size_t)(c0 + cc) * NT + tbase + col4);
            if (BNIN) {
                float s = sc[c0 + cc], h = sh[c0 + cc];
                v.x = fmaxf(0.f, fmaf(v.x, s, h));
                v.y = fmaxf(0.f, fmaf(v.y, s, h));
                v.z = fmaxf(0.f, fmaf(v.z, s, h));
                v.w = fmaxf(0.f, fmaf(v.w, s, h));
            }
            *reinterpret_cast<float4*>(Xs + cc * 256 + col4) = v;
        }
        __syncthreads();
        for (int cc = 0; cc < cn; cc++) {
            float xv[8];
            #pragma unroll
            for (int k = 0; k < 8; k++) xv[k] = Xs[cc * 256 + tx + 32 * k];
            float4 wA = *reinterpret_cast<const float4*>(&WsT[(c0 + cc) * 64 + wp * 8]);
            float4 wB = *reinterpret_cast<const float4*>(&WsT[(c0 + cc) * 64 + wp * 8 + 4]);
            float wv[8] = {wA.x, wA.y, wA.z, wA.w, wB.x, wB.y, wB.z, wB.w};
            #pragma unroll
            for (int j = 0; j < 8; j++)
                #pragma unroll
                for (int k = 0; k < 8; k++)
                    acc[k][j] = fmaf(wv[j], xv[k], acc[k][j]);
        }
    }

    // write Y (coalesced per (j,k): lanes consecutive over tx)
    #pragma unroll
    for (int j = 0; j < 8; j++) {
        const int o = obase + wp * 8 + j;
        float* yp = Yout + (size_t)o * NT + tbase + tx;
        #pragma unroll
        for (int k = 0; k < 8; k++) yp[32 * k] = acc[k][j];
    }

    // fused per-channel partial stats for this block's 256 samples
    #pragma unroll
    for (int j = 0; j < 8; j++) {
        float s = 0.f, q = 0.f;
        #pragma unroll
        for (int k = 0; k < 8; k++) {
            float v = acc[k][j];
            s += v;
            q = fmaf(v, v, q);
        }
        #pragma unroll
        for (int off = 16; off; off >>= 1) {
            s += __shfl_down_sync(0xffffffffu, s, off);
            q += __shfl_down_sync(0xffffffffu, q, off);
        }
        if (tx == 0) {
            const int o = obase + wp * 8 + j;
            g_psum[o * NSTILE + blockIdx.x] = s;
            g_psq [o * NSTILE + blockIdx.x] = q;
        }
    }
}

// ---------------- reduce partials -> BN scale/shift (layers 0,1) ----------
__global__ __launch_bounds__(256) void finalize_kernel(const float* __restrict__ g,
                                                       const float* __restrict__ beta)
{
    const int c = blockIdx.x;
    float s = 0.f, q = 0.f;
    for (int i = threadIdx.x; i < NSTILE; i += 256) {
        s += g_psum[c * NSTILE + i];
        q += g_psq [c * NSTILE + i];
    }
    __shared__ float rs[8], rq[8];
    #pragma unroll
    for (int off = 16; off; off >>= 1) {
        s += __shfl_down_sync(0xffffffffu, s, off);
        q += __shfl_down_sync(0xffffffffu, q, off);
    }
    int w = threadIdx.x >> 5;
    if ((threadIdx.x & 31) == 0) { rs[w] = s; rq[w] = q; }
    __syncthreads();
    if (threadIdx.x == 0) {
        float ts = 0.f, tq = 0.f;
        #pragma unroll
        for (int i = 0; i < 8; i++) { ts += rs[i]; tq += rq[i]; }
        float mu  = ts * (1.0f / NT);
        float var = tq * (1.0f / NT) - mu * mu;
        float rsq = rsqrtf(var + 1e-5f);
        float scv = g[c] * rsq;
        g_scale[c] = scv;
        g_shift[c] = fmaf(-mu, scv, beta[c]);
    }
}

// ---------------- layer-2 BN finalize + BN + ReLU + max over k ------------
// one block per (b, o); derives channel-o scale/shift from partials inline.
__global__ __launch_bounds__(256) void final_kernel(float* __restrict__ out2,
                                                    const float* __restrict__ g,
                                                    const float* __restrict__ beta)
{
    const int bo = blockIdx.x;
    const int b = bo >> 7;
    const int o = bo & 127;
    const int tid  = threadIdx.x;
    const int w    = tid >> 5;
    const int lane = tid & 31;

    __shared__ float rs[8], rq[8];
    __shared__ float s_sc, s_sh;
    {
        float s = 0.f, q = 0.f;
        for (int i = tid; i < NSTILE; i += 256) {
            s += g_psum[o * NSTILE + i];
            q += g_psq [o * NSTILE + i];
        }
        #pragma unroll
        for (int off = 16; off; off >>= 1) {
            s += __shfl_down_sync(0xffffffffu, s, off);
            q += __shfl_down_sync(0xffffffffu, q, off);
        }
        if (lane == 0) { rs[w] = s; rq[w] = q; }
        __syncthreads();
        if (tid == 0) {
            float ts = 0.f, tq = 0.f;
            #pragma unroll
            for (int i = 0; i < 8; i++) { ts += rs[i]; tq += rq[i]; }
            float mu  = ts * (1.0f / NT);
            float var = tq * (1.0f / NT) - mu * mu;
            float rsq = rsqrtf(var + 1e-5f);
            float scv = g[o] * rsq;
            s_sc = scv;
            s_sh = fmaf(-mu, scv, beta[o]);
        }
        __syncthreads();
    }
    const float scv = s_sc;
    const float shv = s_sh;

    const float* p = g_Y2 + (size_t)o * NT + (size_t)b * (NPOINT * NSAMPLE);
    for (int r = 0; r < 64; r++) {
        float v = p[tid + r * 256];
        v = fmaxf(0.f, fmaf(v, scv, shv));
        #pragma unroll
        for (int off = 16; off; off >>= 1)
            v = fmaxf(v, __shfl_down_sync(0xffffffffu, v, off));
        if (lane == 0)
            out2[(b * 128 + o) * NPOINT + (w + 8 * r)] = v;
    }
}

// ---------------- launch ----------------
extern "C" void kernel_launch(void* const* d_in, const int* in_sizes, int n_in,
                              void* d_out, int out_size)
{
    (void)in_sizes; (void)n_in; (void)out_size;
    const float* xyz    = (const float*)d_in[0];
    const float* points = (const float*)d_in[1];
    const float* W0 = (const float*)d_in[2];
    const float* b0 = (const float*)d_in[3];
    const float* g0 = (const float*)d_in[4];
    const float* be0= (const float*)d_in[5];
    const float* W1 = (const float*)d_in[6];
    const float* b1 = (const float*)d_in[7];
    const float* g1 = (const float*)d_in[8];
    const float* be1= (const float*)d_in[9];
    const float* W2 = (const float*)d_in[10];
    const float* b2 = (const float*)d_in[11];
    const float* g2 = (const float*)d_in[12];
    const float* be2= (const float*)d_in[13];

    float* out = (float*)d_out;

    fps_kernel<<<BATCH, 1024>>>(xyz, out);
    ball_gather_kernel<<<(BATCH * NPOINT) / 8, 256>>>(xyz, points);

    layer_kernel<67, false, 0><<<dim3(NSTILE, 1), 256>>>(W0, b0);
    finalize_kernel<<<64, 256>>>(g0, be0);

    layer_kernel<64, true, 1><<<dim3(NSTILE, 1), 256>>>(W1, b1);
    finalize_kernel<<<64, 256>>>(g1, be1);

    layer_kernel<64, true, 2><<<dim3(NSTILE, 2), 256>>>(W2, b2);

    final_kernel<<<BATCH * 128, 256>>>(out + BATCH * 3 * NPOINT, g2, be2);
}

// round 6
// speedup vs baseline: 1.4157x; 1.0694x over previous
#include <cuda_runtime.h>

#define NPTS    8192
#define BATCH   8
#define NPOINT  512
#define NSAMPLE 32
#define NT      (BATCH*NPOINT*NSAMPLE)   // 131072 samples
#define NSTILE  512                      // sample tiles of 256 in layer kernels

// ---------------- scratch (device globals; no allocation) ----------------
__device__ float g_X0[67u*NT];    // layer0 input features [c][t]
__device__ float g_Y0[64u*NT];    // layer0 raw output (pre-BN)
__device__ float g_Y1[64u*NT];    // layer1 raw output
__device__ float g_Y2[128u*NT];   // layer2 raw output
__device__ float g_newxyz[BATCH*NPOINT*3];   // (b,s,3) centroids
__device__ float g_psum[128*NSTILE];
__device__ float g_psq [128*NSTILE];
__device__ float g_scale[128];
__device__ float g_shift[128];

// ---------------- packed f32x2 helpers (per-half rounding == scalar ops) ---
typedef unsigned long long u64;
__device__ __forceinline__ u64 pk2(float lo, float hi) {
    u64 r; asm("mov.b64 %0,{%1,%2};" : "=l"(r) : "f"(lo), "f"(hi)); return r;
}
__device__ __forceinline__ void upk2(u64 v, float& lo, float& hi) {
    asm("mov.b64 {%0,%1},%2;" : "=f"(lo), "=f"(hi) : "l"(v));
}
__device__ __forceinline__ u64 add2(u64 a, u64 b) {
    u64 r; asm("add.rn.f32x2 %0,%1,%2;" : "=l"(r) : "l"(a), "l"(b)); return r;
}
__device__ __forceinline__ u64 mul2(u64 a, u64 b) {
    u64 r; asm("mul.rn.f32x2 %0,%1,%2;" : "=l"(r) : "l"(a), "l"(b)); return r;
}
__device__ __forceinline__ u64 fma2(u64 a, u64 b, u64 c) {
    u64 r; asm("fma.rn.f32x2 %0,%1,%2,%3;" : "=l"(r) : "l"(a), "l"(b), "l"(c)); return r;
}

// butterfly argmax: after this, EVERY lane holds the warp's (max value,
// first index). Tie-break: smaller index wins (matches jnp.argmax).
__device__ __forceinline__ void warp_argmax_bfly(float& v, int& i) {
    #pragma unroll
    for (int off = 16; off; off >>= 1) {
        float v2 = __shfl_xor_sync(0xffffffffu, v, off);
        int   i2 = __shfl_xor_sync(0xffffffffu, i, off);
        if (v2 > v || (v2 == v && i2 < i)) { v = v2; i = i2; }
    }
}

// ---------------- FPS ----------------
// One CTA per batch, 512 threads (16 warps), 16 points/thread in packed
// f32x2 registers. Per iteration: FMNMX min-update (bit-exact formula,
// verified rounds 1/2/4), 15-op max tree + descending equality scan
// (round-4-verified argmax semantics), bfly warp reduce, ONE barrier with
// parity double-buffered partials, all-warps-redundant stage 2.
__global__ __launch_bounds__(512) void fps_kernel(const float* __restrict__ xyz,
                                                  float* __restrict__ out_newxyz)
{
    const int b    = blockIdx.x;
    const int tid  = threadIdx.x;
    const int lane = tid & 31;
    const int w    = tid >> 5;           // 0..15
    const float* X  = xyz + (size_t)b * 3 * NPTS;
    const float* Yc = X + NPTS;
    const float* Z  = X + 2 * NPTS;

    u64 px2[8], py2[8], pz2[8];
    float dist[16];
    #pragma unroll
    for (int m = 0; m < 8; m++) {
        int i0 = tid + (2 * m) * 512, i1 = i0 + 512;
        px2[m] = pk2(X[i0],  X[i1]);
        py2[m] = pk2(Yc[i0], Yc[i1]);
        pz2[m] = pk2(Z[i0],  Z[i1]);
        dist[2 * m] = 1e10f; dist[2 * m + 1] = 1e10f;
    }

    __shared__ float s_v[2][32];
    __shared__ int   s_i[2][32];
    // pad slots 16..31 of both parities (16 warps only)
    if (tid >= 16 && tid < 32) {
        s_v[0][tid] = -1e30f; s_v[1][tid] = -1e30f;
        s_i[0][tid] = 0x7fffffff; s_i[1][tid] = 0x7fffffff;
    }

    // ---- init: far = argmax over x (first-index ties) ----
    int far;
    {
        float bv = -1e30f; int bi = 0;
        #pragma unroll
        for (int m = 0; m < 8; m++) {
            float x0, x1; upk2(px2[m], x0, x1);
            int i0 = tid + (2 * m) * 512;
            if (x0 > bv) { bv = x0; bi = i0; }
            if (x1 > bv) { bv = x1; bi = i0 + 512; }
        }
        warp_argmax_bfly(bv, bi);
        if (lane == 0) { s_v[1][w] = bv; s_i[1][w] = bi; }
        __syncthreads();
        float v2 = s_v[1][lane]; int i2 = s_i[1][lane];
        warp_argmax_bfly(v2, i2);
        far = i2;
    }

    for (int s = 0; s < NPOINT; s++) {
        const float cx = X[far], cy = Yc[far], cz = Z[far];
        if (tid == 0) {
            out_newxyz[(b * 3 + 0) * NPOINT + s] = cx;
            out_newxyz[(b * 3 + 1) * NPOINT + s] = cy;
            out_newxyz[(b * 3 + 2) * NPOINT + s] = cz;
            g_newxyz[(b * NPOINT + s) * 3 + 0] = cx;
            g_newxyz[(b * NPOINT + s) * 3 + 1] = cy;
            g_newxyz[(b * NPOINT + s) * 3 + 2] = cz;
        }
        const u64 ncx2 = pk2(-cx, -cx);
        const u64 ncy2 = pk2(-cy, -cy);
        const u64 ncz2 = pk2(-cz, -cz);
        #pragma unroll
        for (int m = 0; m < 8; m++) {
            u64 dx2 = add2(px2[m], ncx2);          // rn(px - cx) per half
            u64 dy2 = add2(py2[m], ncy2);
            u64 dz2 = add2(pz2[m], ncz2);
            u64 d2  = fma2(dz2, dz2, fma2(dy2, dy2, mul2(dx2, dx2)));
            float d0, d1; upk2(d2, d0, d1);
            dist[2 * m]     = fminf(dist[2 * m],     d0);
            dist[2 * m + 1] = fminf(dist[2 * m + 1], d1);
        }
        // local max (tree), then first matching index (descending j)
        float m01 = fmaxf(dist[0], dist[1]),   m23 = fmaxf(dist[2], dist[3]);
        float m45 = fmaxf(dist[4], dist[5]),   m67 = fmaxf(dist[6], dist[7]);
        float m89 = fmaxf(dist[8], dist[9]),   mab = fmaxf(dist[10], dist[11]);
        float mcd = fmaxf(dist[12], dist[13]), mef = fmaxf(dist[14], dist[15]);
        float lv = fmaxf(fmaxf(fmaxf(m01, m23), fmaxf(m45, m67)),
                         fmaxf(fmaxf(m89, mab), fmaxf(mcd, mef)));
        int li = 0x7fffffff;
        #pragma unroll
        for (int j = 15; j >= 0; j--)
            if (dist[j] == lv) li = tid + j * 512;

        warp_argmax_bfly(lv, li);
        const int p = s & 1;
        if (lane == 0) { s_v[p][w] = lv; s_i[p][w] = li; }
        __syncthreads();
        float v2 = s_v[p][lane]; int i2 = s_i[p][lane];
        warp_argmax_bfly(v2, i2);
        far = i2;
    }
}

// ---------------- ball query + gather (one warp per (b,s)) ----------------
// Distance rounds EXACTLY like the reference (verified):
//   dot  = fma(c2,p2, fma(c1,p1, rn(c0*p0)))
//   |v|^2 = rn(rn(x*x + y*y) + z*z)  built from plain mul/add (NO fma)
//   d    = rn(rn(-2*dot + |src|^2) + |dst|^2)
__global__ __launch_bounds__(256) void ball_gather_kernel(const float* __restrict__ xyz,
                                                          const float* __restrict__ points)
{
    const int w    = blockIdx.x * 8 + (threadIdx.x >> 5);
    const int lane = threadIdx.x & 31;
    const int b = w >> 9;
    const int s = w & 511;

    const float* X  = xyz + (size_t)b * 3 * NPTS;
    const float* Yc = X + NPTS;
    const float* Z  = X + 2 * NPTS;

    const float cx = g_newxyz[(b * NPOINT + s) * 3 + 0];
    const float cy = g_newxyz[(b * NPOINT + s) * 3 + 1];
    const float cz = g_newxyz[(b * NPOINT + s) * 3 + 2];
    const float cc = __fadd_rn(__fadd_rn(__fmul_rn(cx, cx), __fmul_rn(cy, cy)),
                               __fmul_rn(cz, cz));
    const float r2 = 0.04f;

    __shared__ int nbr_s[8][NSAMPLE];
    int* nbr = nbr_s[threadIdx.x >> 5];

    int found = 0;
    for (int base = 0; base < NPTS; base += 32) {
        int   j  = base + lane;
        float xj = X[j], yj = Yc[j], zj = Z[j];
        float dot = fmaf(cz, zj, fmaf(cy, yj, __fmul_rn(cx, xj)));
        float pp  = __fadd_rn(__fadd_rn(__fmul_rn(xj, xj), __fmul_rn(yj, yj)),
                              __fmul_rn(zj, zj));
        float d   = __fadd_rn(__fadd_rn(__fmul_rn(-2.0f, dot), cc), pp);
        bool in   = !(d > r2);
        unsigned m = __ballot_sync(0xffffffffu, in);
        int pos = found + __popc(m & ((1u << lane) - 1u));
        if (in && pos < NSAMPLE) nbr[pos] = j;
        found += __popc(m);
        if (found >= NSAMPLE) break;
    }
    __syncwarp();
    if (found > NSAMPLE) found = NSAMPLE;
    int j0 = nbr[0];
    int j  = (lane < found) ? nbr[lane] : j0;

    const int t = (b * NPOINT + s) * NSAMPLE + lane;
    g_X0[0u * NT + t] = X[j]  - cx;
    g_X0[1u * NT + t] = Yc[j] - cy;
    g_X0[2u * NT + t] = Z[j]  - cz;
    const float* P = points + (size_t)b * 64 * NPTS;
    #pragma unroll 4
    for (int d = 0; d < 64; d++) {
        g_X0[(size_t)(3 + d) * NT + t] = P[(size_t)d * NPTS + j];
    }
}

// ---------------- fused layer GEMM, 8x8 register blocked, fused BN stats ---
// Block = 256 threads (tx=lane 0..31, warp wp=0..7). Tile = 256 samples x 64
// outputs. Thread computes 8 samples (tx + 32k) x 8 outputs (wp*8+j).
// Weights staged TRANSPOSED (WsT[c][o]) so the 8 per-cc weights are fetched
// as 2 broadcast LDS.128. Input BN+ReLU applied once at X staging. Epilogue
// emits per-block per-channel sum/sumsq partials (deterministic, no atomics).
#define CCH 16
template<int CIN, bool BNIN, int LAYER>
__global__ __launch_bounds__(256, 2) void layer_kernel(const float* __restrict__ W,
                                                       const float* __restrict__ bias)
{
    const float* Xin  = (LAYER == 0) ? g_X0 : (LAYER == 1) ? g_Y0 : g_Y1;
    float*       Yout = (LAYER == 0) ? g_Y0 : (LAYER == 1) ? g_Y1 : g_Y2;

    __shared__ __align__(16) float WsT[CIN * 64];   // [c][o]
    __shared__ float bs2[64];
    __shared__ float Xs[CCH * 256];
    __shared__ float sc[CIN];
    __shared__ float sh[CIN];

    const int tid   = threadIdx.x;
    const int tx    = tid & 31;
    const int wp    = tid >> 5;
    const int obase = blockIdx.y * 64;
    const int tbase = blockIdx.x * 256;

    // transpose-stage W: i -> (o = i & 63, c = i >> 6); STS conflict-free.
    const float* Wg = W + (size_t)obase * CIN;
    for (int i = tid; i < 64 * CIN; i += 256) {
        int o = i & 63, c = i >> 6;
        WsT[c * 64 + o] = Wg[o * CIN + c];
    }
    for (int i = tid; i < 64; i += 256) bs2[i] = bias[obase + i];
    if (BNIN) {
        for (int i = tid; i < CIN; i += 256) { sc[i] = g_scale[i]; sh[i] = g_shift[i]; }
    }
    __syncthreads();

    float acc[8][8];
    {
        float b0[8];
        #pragma unroll
        for (int j = 0; j < 8; j++) b0[j] = bs2[wp * 8 + j];
        #pragma unroll
        for (int k = 0; k < 8; k++)
            #pragma unroll
            for (int j = 0; j < 8; j++) acc[k][j] = b0[j];
    }

    for (int c0 = 0; c0 < CIN; c0 += CCH) {
        const int cn = (CIN - c0 < CCH) ? (CIN - c0) : CCH;
        __syncthreads();
        for (int e = tid; e < cn * 64; e += 256) {
            int cc   = e >> 6;
            int col4 = (e & 63) << 2;
            float4 v = *reinterpret_cast<const float4*>(
                Xin + (size_t)(c0 + cc) * NT + tbase + col4);
            if (BNIN) {
                float s = sc[c0 + cc], h = sh[c0 + cc];
                v.x = fmaxf(0.f, fmaf(v.x, s, h));
                v.y = fmaxf(0.f, fmaf(v.y, s, h));
                v.z = fmaxf(0.f, fmaf(v.z, s, h));
                v.w = fmaxf(0.f, fmaf(v.w, s, h));
            }
            *reinterpret_cast<float4*>(Xs + cc * 256 + col4) = v;
        }
        __syncthreads();
        for (int cc = 0; cc < cn; cc++) {
            float xv[8];
            #pragma unroll
            for (int k = 0; k < 8; k++) xv[k] = Xs[cc * 256 + tx + 32 * k];
            float4 wA = *reinterpret_cast<const float4*>(&WsT[(c0 + cc) * 64 + wp * 8]);
            float4 wB = *reinterpret_cast<const float4*>(&WsT[(c0 + cc) * 64 + wp * 8 + 4]);
            float wv[8] = {wA.x, wA.y, wA.z, wA.w, wB.x, wB.y, wB.z, wB.w};
            #pragma unroll
            for (int j = 0; j < 8; j++)
                #pragma unroll
                for (int k = 0; k < 8; k++)
                    acc[k][j] = fmaf(wv[j], xv[k], acc[k][j]);
        }
    }

    // write Y (coalesced per (j,k): lanes consecutive over tx)
    #pragma unroll
    for (int j = 0; j < 8; j++) {
        const int o = obase + wp * 8 + j;
        float* yp = Yout + (size_t)o * NT + tbase + tx;
        #pragma unroll
        for (int k = 0; k < 8; k++) yp[32 * k] = acc[k][j];
    }

    // fused per-channel partial stats for this block's 256 samples
    #pragma unroll
    for (int j = 0; j < 8; j++) {
        float s = 0.f, q = 0.f;
        #pragma unroll
        for (int k = 0; k < 8; k++) {
            float v = acc[k][j];
            s += v;
            q = fmaf(v, v, q);
        }
        #pragma unroll
        for (int off = 16; off; off >>= 1) {
            s += __shfl_down_sync(0xffffffffu, s, off);
            q += __shfl_down_sync(0xffffffffu, q, off);
        }
        if (tx == 0) {
            const int o = obase + wp * 8 + j;
            g_psum[o * NSTILE + blockIdx.x] = s;
            g_psq [o * NSTILE + blockIdx.x] = q;
        }
    }
}

// ---------------- reduce partials -> BN scale/shift (layers 0,1) ----------
__global__ __launch_bounds__(256) void finalize_kernel(const float* __restrict__ g,
                                                       const float* __restrict__ beta)
{
    const int c = blockIdx.x;
    float s = 0.f, q = 0.f;
    for (int i = threadIdx.x; i < NSTILE; i += 256) {
        s += g_psum[c * NSTILE + i];
        q += g_psq [c * NSTILE + i];
    }
    __shared__ float rs[8], rq[8];
    #pragma unroll
    for (int off = 16; off; off >>= 1) {
        s += __shfl_down_sync(0xffffffffu, s, off);
        q += __shfl_down_sync(0xffffffffu, q, off);
    }
    int w = threadIdx.x >> 5;
    if ((threadIdx.x & 31) == 0) { rs[w] = s; rq[w] = q; }
    __syncthreads();
    if (threadIdx.x == 0) {
        float ts = 0.f, tq = 0.f;
        #pragma unroll
        for (int i = 0; i < 8; i++) { ts += rs[i]; tq += rq[i]; }
        float mu  = ts * (1.0f / NT);
        float var = tq * (1.0f / NT) - mu * mu;
        float rsq = rsqrtf(var + 1e-5f);
        float scv = g[c] * rsq;
        g_scale[c] = scv;
        g_shift[c] = fmaf(-mu, scv, beta[c]);
    }
}

// ---------------- layer-2 BN finalize + BN + ReLU + max over k ------------
// one block per (b, o); derives channel-o scale/shift from partials inline.
__global__ __launch_bounds__(256) void final_kernel(float* __restrict__ out2,
                                                    const float* __restrict__ g,
                                                    const float* __restrict__ beta)
{
    const int bo = blockIdx.x;
    const int b = bo >> 7;
    const int o = bo & 127;
    const int tid  = threadIdx.x;
    const int w    = tid >> 5;
    const int lane = tid & 31;

    __shared__ float rs[8], rq[8];
    __shared__ float s_sc, s_sh;
    {
        float s = 0.f, q = 0.f;
        for (int i = tid; i < NSTILE; i += 256) {
            s += g_psum[o * NSTILE + i];
            q += g_psq [o * NSTILE + i];
        }
        #pragma unroll
        for (int off = 16; off; off >>= 1) {
            s += __shfl_down_sync(0xffffffffu, s, off);
            q += __shfl_down_sync(0xffffffffu, q, off);
        }
        if (lane == 0) { rs[w] = s; rq[w] = q; }
        __syncthreads();
        if (tid == 0) {
            float ts = 0.f, tq = 0.f;
            #pragma unroll
            for (int i = 0; i < 8; i++) { ts += rs[i]; tq += rq[i]; }
            float mu  = ts * (1.0f / NT);
            float var = tq * (1.0f / NT) - mu * mu;
            float rsq = rsqrtf(var + 1e-5f);
            float scv = g[o] * rsq;
            s_sc = scv;
            s_sh = fmaf(-mu, scv, beta[o]);
        }
        __syncthreads();
    }
    const float scv = s_sc;
    const float shv = s_sh;

    const float* p = g_Y2 + (size_t)o * NT + (size_t)b * (NPOINT * NSAMPLE);
    for (int r = 0; r < 64; r++) {
        float v = p[tid + r * 256];
        v = fmaxf(0.f, fmaf(v, scv, shv));
        #pragma unroll
        for (int off = 16; off; off >>= 1)
            v = fmaxf(v, __shfl_down_sync(0xffffffffu, v, off));
        if (lane == 0)
            out2[(b * 128 + o) * NPOINT + (w + 8 * r)] = v;
    }
}

// ---------------- launch ----------------
extern "C" void kernel_launch(void* const* d_in, const int* in_sizes, int n_in,
                              void* d_out, int out_size)
{
    (void)in_sizes; (void)n_in; (void)out_size;
    const float* xyz    = (const float*)d_in[0];
    const float* points = (const float*)d_in[1];
    const float* W0 = (const float*)d_in[2];
    const float* b0 = (const float*)d_in[3];
    const float* g0 = (const float*)d_in[4];
    const float* be0= (const float*)d_in[5];
    const float* W1 = (const float*)d_in[6];
    const float* b1 = (const float*)d_in[7];
    const float* g1 = (const float*)d_in[8];
    const float* be1= (const float*)d_in[9];
    const float* W2 = (const float*)d_in[10];
    const float* b2 = (const float*)d_in[11];
    const float* g2 = (const float*)d_in[12];
    const float* be2= (const float*)d_in[13];

    float* out = (float*)d_out;

    fps_kernel<<<BATCH, 512>>>(xyz, out);
    ball_gather_kernel<<<(BATCH * NPOINT) / 8, 256>>>(xyz, points);

    layer_kernel<67, false, 0><<<dim3(NSTILE, 1), 256>>>(W0, b0);
    finalize_kernel<<<64, 256>>>(g0, be0);

    layer_kernel<64, true, 1><<<dim3(NSTILE, 1), 256>>>(W1, b1);
    finalize_kernel<<<64, 256>>>(g1, be1);

    layer_kernel<64, true, 2><<<dim3(NSTILE, 2), 256>>>(W2, b2);

    final_kernel<<<BATCH * 128, 256>>>(out + BATCH * 3 * NPOINT, g2, be2);
}

// round 7
// speedup vs baseline: 1.4685x; 1.0373x over previous
#include <cuda_runtime.h>

#define NPTS    8192
#define BATCH   8
#define NPOINT  512
#define NSAMPLE 32
#define NT      (BATCH*NPOINT*NSAMPLE)   // 131072 samples
#define NSTILE  512                      // sample tiles of 256 in layer kernels

// ---------------- scratch (device globals; no allocation) ----------------
__device__ float g_X0[67u*NT];    // layer0 input features [c][t]
__device__ float g_Y0[64u*NT];    // layer0 raw output (pre-BN)
__device__ float g_Y1[64u*NT];    // layer1 raw output
__device__ float g_Y2[128u*NT];   // layer2 raw output
__device__ float g_newxyz[BATCH*NPOINT*3];   // (b,s,3) centroids
__device__ float g_psum[128*NSTILE];
__device__ float g_psq [128*NSTILE];
__device__ float g_scale[128];
__device__ float g_shift[128];

// ---------------- packed f32x2 helpers (per-half rounding == scalar ops) ---
typedef unsigned long long u64;
__device__ __forceinline__ u64 pk2(float lo, float hi) {
    u64 r; asm("mov.b64 %0,{%1,%2};" : "=l"(r) : "f"(lo), "f"(hi)); return r;
}
__device__ __forceinline__ void upk2(u64 v, float& lo, float& hi) {
    asm("mov.b64 {%0,%1},%2;" : "=f"(lo), "=f"(hi) : "l"(v));
}
__device__ __forceinline__ u64 add2(u64 a, u64 b) {
    u64 r; asm("add.rn.f32x2 %0,%1,%2;" : "=l"(r) : "l"(a), "l"(b)); return r;
}
__device__ __forceinline__ u64 mul2(u64 a, u64 b) {
    u64 r; asm("mul.rn.f32x2 %0,%1,%2;" : "=l"(r) : "l"(a), "l"(b)); return r;
}
__device__ __forceinline__ u64 fma2(u64 a, u64 b, u64 c) {
    u64 r; asm("fma.rn.f32x2 %0,%1,%2,%3;" : "=l"(r) : "l"(a), "l"(b), "l"(c)); return r;
}

// butterfly argmax: after this, EVERY lane holds the warp's (max value,
// first index). Tie-break: smaller index wins (matches jnp.argmax).
__device__ __forceinline__ void warp_argmax_bfly(float& v, int& i) {
    #pragma unroll
    for (int off = 16; off; off >>= 1) {
        float v2 = __shfl_xor_sync(0xffffffffu, v, off);
        int   i2 = __shfl_xor_sync(0xffffffffu, i, off);
        if (v2 > v || (v2 == v && i2 < i)) { v = v2; i = i2; }
    }
}

// 16-wide butterfly (values mirrored across half-warps)
__device__ __forceinline__ void warp_argmax_bfly16(float& v, int& i) {
    #pragma unroll
    for (int off = 8; off; off >>= 1) {
        float v2 = __shfl_xor_sync(0xffffffffu, v, off);
        int   i2 = __shfl_xor_sync(0xffffffffu, i, off);
        if (v2 > v || (v2 == v && i2 < i)) { v = v2; i = i2; }
    }
}

// ---------------- FPS ----------------
// One CTA per batch, 512 threads (16 warps), 16 points/thread in packed
// f32x2 registers. Per iteration: FMNMX min-update (bit-exact formula),
// 15-op max tree + descending equality scan, bfly warp reduce, ONE barrier
// with parity double-buffered partials, all-warps 16-wide stage 2.
__global__ __launch_bounds__(512) void fps_kernel(const float* __restrict__ xyz,
                                                  float* __restrict__ out_newxyz)
{
    const int b    = blockIdx.x;
    const int tid  = threadIdx.x;
    const int lane = tid & 31;
    const int w    = tid >> 5;           // 0..15
    const float* X  = xyz + (size_t)b * 3 * NPTS;
    const float* Yc = X + NPTS;
    const float* Z  = X + 2 * NPTS;

    u64 px2[8], py2[8], pz2[8];
    float dist[16];
    #pragma unroll
    for (int m = 0; m < 8; m++) {
        int i0 = tid + (2 * m) * 512, i1 = i0 + 512;
        px2[m] = pk2(X[i0],  X[i1]);
        py2[m] = pk2(Yc[i0], Yc[i1]);
        pz2[m] = pk2(Z[i0],  Z[i1]);
        dist[2 * m] = 1e10f; dist[2 * m + 1] = 1e10f;
    }

    __shared__ float s_v[2][16];
    __shared__ int   s_i[2][16];

    // ---- init: far = argmax over x (first-index ties) ----
    int far;
    {
        float bv = -1e30f; int bi = 0;
        #pragma unroll
        for (int m = 0; m < 8; m++) {
            float x0, x1; upk2(px2[m], x0, x1);
            int i0 = tid + (2 * m) * 512;
            if (x0 > bv) { bv = x0; bi = i0; }
            if (x1 > bv) { bv = x1; bi = i0 + 512; }
        }
        warp_argmax_bfly(bv, bi);
        if (lane == 0) { s_v[1][w] = bv; s_i[1][w] = bi; }
        __syncthreads();
        float v2 = s_v[1][lane & 15]; int i2 = s_i[1][lane & 15];
        warp_argmax_bfly16(v2, i2);
        far = i2;
    }

    for (int s = 0; s < NPOINT; s++) {
        const float cx = X[far], cy = Yc[far], cz = Z[far];
        if (tid == 0) {
            out_newxyz[(b * 3 + 0) * NPOINT + s] = cx;
            out_newxyz[(b * 3 + 1) * NPOINT + s] = cy;
            out_newxyz[(b * 3 + 2) * NPOINT + s] = cz;
            g_newxyz[(b * NPOINT + s) * 3 + 0] = cx;
            g_newxyz[(b * NPOINT + s) * 3 + 1] = cy;
            g_newxyz[(b * NPOINT + s) * 3 + 2] = cz;
        }
        const u64 ncx2 = pk2(-cx, -cx);
        const u64 ncy2 = pk2(-cy, -cy);
        const u64 ncz2 = pk2(-cz, -cz);
        #pragma unroll
        for (int m = 0; m < 8; m++) {
            u64 dx2 = add2(px2[m], ncx2);          // rn(px - cx) per half
            u64 dy2 = add2(py2[m], ncy2);
            u64 dz2 = add2(pz2[m], ncz2);
            u64 d2  = fma2(dz2, dz2, fma2(dy2, dy2, mul2(dx2, dx2)));
            float d0, d1; upk2(d2, d0, d1);
            dist[2 * m]     = fminf(dist[2 * m],     d0);
            dist[2 * m + 1] = fminf(dist[2 * m + 1], d1);
        }
        // local max (tree), then first matching index (descending j)
        float m01 = fmaxf(dist[0], dist[1]),   m23 = fmaxf(dist[2], dist[3]);
        float m45 = fmaxf(dist[4], dist[5]),   m67 = fmaxf(dist[6], dist[7]);
        float m89 = fmaxf(dist[8], dist[9]),   mab = fmaxf(dist[10], dist[11]);
        float mcd = fmaxf(dist[12], dist[13]), mef = fmaxf(dist[14], dist[15]);
        float lv = fmaxf(fmaxf(fmaxf(m01, m23), fmaxf(m45, m67)),
                         fmaxf(fmaxf(m89, mab), fmaxf(mcd, mef)));
        int li = 0x7fffffff;
        #pragma unroll
        for (int j = 15; j >= 0; j--)
            if (dist[j] == lv) li = tid + j * 512;

        warp_argmax_bfly(lv, li);
        const int p = s & 1;
        if (lane == 0) { s_v[p][w] = lv; s_i[p][w] = li; }
        __syncthreads();
        float v2 = s_v[p][lane & 15]; int i2 = s_i[p][lane & 15];
        warp_argmax_bfly16(v2, i2);
        far = i2;
    }
}

// ---------------- ball query + gather (one warp per (b,s)) ----------------
// Distance rounds EXACTLY like the reference (verified):
//   dot  = fma(c2,p2, fma(c1,p1, rn(c0*p0)))
//   |v|^2 = rn(rn(x*x + y*y) + z*z)  built from plain mul/add (NO fma)
//   d    = rn(rn(-2*dot + |src|^2) + |dst|^2)
__global__ __launch_bounds__(256) void ball_gather_kernel(const float* __restrict__ xyz,
                                                          const float* __restrict__ points)
{
    const int w    = blockIdx.x * 8 + (threadIdx.x >> 5);
    const int lane = threadIdx.x & 31;
    const int b = w >> 9;
    const int s = w & 511;

    const float* X  = xyz + (size_t)b * 3 * NPTS;
    const float* Yc = X + NPTS;
    const float* Z  = X + 2 * NPTS;

    const float cx = g_newxyz[(b * NPOINT + s) * 3 + 0];
    const float cy = g_newxyz[(b * NPOINT + s) * 3 + 1];
    const float cz = g_newxyz[(b * NPOINT + s) * 3 + 2];
    const float cc = __fadd_rn(__fadd_rn(__fmul_rn(cx, cx), __fmul_rn(cy, cy)),
                               __fmul_rn(cz, cz));
    const float r2 = 0.04f;

    __shared__ int nbr_s[8][NSAMPLE];
    int* nbr = nbr_s[threadIdx.x >> 5];

    int found = 0;
    for (int base = 0; base < NPTS; base += 32) {
        int   j  = base + lane;
        float xj = X[j], yj = Yc[j], zj = Z[j];
        float dot = fmaf(cz, zj, fmaf(cy, yj, __fmul_rn(cx, xj)));
        float pp  = __fadd_rn(__fadd_rn(__fmul_rn(xj, xj), __fmul_rn(yj, yj)),
                              __fmul_rn(zj, zj));
        float d   = __fadd_rn(__fadd_rn(__fmul_rn(-2.0f, dot), cc), pp);
        bool in   = !(d > r2);
        unsigned m = __ballot_sync(0xffffffffu, in);
        int pos = found + __popc(m & ((1u << lane) - 1u));
        if (in && pos < NSAMPLE) nbr[pos] = j;
        found += __popc(m);
        if (found >= NSAMPLE) break;
    }
    __syncwarp();
    if (found > NSAMPLE) found = NSAMPLE;
    int j0 = nbr[0];
    int j  = (lane < found) ? nbr[lane] : j0;

    const int t = (b * NPOINT + s) * NSAMPLE + lane;
    g_X0[0u * NT + t] = X[j]  - cx;
    g_X0[1u * NT + t] = Yc[j] - cy;
    g_X0[2u * NT + t] = Z[j]  - cz;
    const float* P = points + (size_t)b * 64 * NPTS;
    #pragma unroll 4
    for (int d = 0; d < 64; d++) {
        g_X0[(size_t)(3 + d) * NT + t] = P[(size_t)d * NPTS + j];
    }
}

// ---------------- fused layer GEMM, f32x2-packed, fused BN stats ----------
// Block = 256 threads (tx=lane 0..31, warp wp=0..7). Tile = 256 samples x 64
// outputs. Thread computes 4 ADJACENT-SAMPLE PAIRS (samples 2tx, 2tx+1 at
// k*64 offsets) x 8 outputs, accumulated with fma.rn.f32x2 (2 FMAs/issue,
// per-half rounding identical to scalar FFMA). x pairs load as LDS.64 with
// no packing; weights packed (w,w) once per cc. Stores are STG.64 coalesced.
// Epilogue emits per-block per-channel sum/sumsq partials (no atomics).
#define CCH 16
template<int CIN, bool BNIN, int LAYER>
__global__ __launch_bounds__(256, 2) void layer_kernel(const float* __restrict__ W,
                                                       const float* __restrict__ bias)
{
    const float* Xin  = (LAYER == 0) ? g_X0 : (LAYER == 1) ? g_Y0 : g_Y1;
    float*       Yout = (LAYER == 0) ? g_Y0 : (LAYER == 1) ? g_Y1 : g_Y2;

    __shared__ __align__(16) float WsT[CIN * 64];   // [c][o]
    __shared__ float bs2[64];
    __shared__ __align__(16) float Xs[CCH * 256];
    __shared__ float sc[CIN];
    __shared__ float sh[CIN];

    const int tid   = threadIdx.x;
    const int tx    = tid & 31;
    const int wp    = tid >> 5;
    const int obase = blockIdx.y * 64;
    const int tbase = blockIdx.x * 256;

    // transpose-stage W: i -> (o = i & 63, c = i >> 6); STS conflict-free.
    const float* Wg = W + (size_t)obase * CIN;
    for (int i = tid; i < 64 * CIN; i += 256) {
        int o = i & 63, c = i >> 6;
        WsT[c * 64 + o] = Wg[o * CIN + c];
    }
    for (int i = tid; i < 64; i += 256) bs2[i] = bias[obase + i];
    if (BNIN) {
        for (int i = tid; i < CIN; i += 256) { sc[i] = g_scale[i]; sh[i] = g_shift[i]; }
    }
    __syncthreads();

    // acc2[k][j]: sample pair (tbase + 64k + 2tx, +1), output obase + wp*8 + j
    u64 acc2[4][8];
    #pragma unroll
    for (int j = 0; j < 8; j++) {
        float b0 = bs2[wp * 8 + j];
        u64 bb = pk2(b0, b0);
        #pragma unroll
        for (int k = 0; k < 4; k++) acc2[k][j] = bb;
    }

    for (int c0 = 0; c0 < CIN; c0 += CCH) {
        const int cn = (CIN - c0 < CCH) ? (CIN - c0) : CCH;
        __syncthreads();
        for (int e = tid; e < cn * 64; e += 256) {
            int cc   = e >> 6;
            int col4 = (e & 63) << 2;
            float4 v = *reinterpret_cast<const float4*>(
                Xin + (size_t)(c0 + cc) * NT + tbase + col4);
            if (BNIN) {
                float s = sc[c0 + cc], h = sh[c0 + cc];
                v.x = fmaxf(0.f, fmaf(v.x, s, h));
                v.y = fmaxf(0.f, fmaf(v.y, s, h));
                v.z = fmaxf(0.f, fmaf(v.z, s, h));
                v.w = fmaxf(0.f, fmaf(v.w, s, h));
            }
            *reinterpret_cast<float4*>(Xs + cc * 256 + col4) = v;
        }
        __syncthreads();
        for (int cc = 0; cc < cn; cc++) {
            u64 x2[4];
            #pragma unroll
            for (int k = 0; k < 4; k++)
                x2[k] = *reinterpret_cast<const u64*>(&Xs[cc * 256 + 64 * k + 2 * tx]);
            float4 wA = *reinterpret_cast<const float4*>(&WsT[(c0 + cc) * 64 + wp * 8]);
            float4 wB = *reinterpret_cast<const float4*>(&WsT[(c0 + cc) * 64 + wp * 8 + 4]);
            u64 w2[8] = {pk2(wA.x, wA.x), pk2(wA.y, wA.y), pk2(wA.z, wA.z), pk2(wA.w, wA.w),
                         pk2(wB.x, wB.x), pk2(wB.y, wB.y), pk2(wB.z, wB.z), pk2(wB.w, wB.w)};
            #pragma unroll
            for (int j = 0; j < 8; j++)
                #pragma unroll
                for (int k = 0; k < 4; k++)
                    acc2[k][j] = fma2(w2[j], x2[k], acc2[k][j]);
        }
    }

    // write Y (STG.64, coalesced: lanes write adjacent 8B)
    #pragma unroll
    for (int j = 0; j < 8; j++) {
        const int o = obase + wp * 8 + j;
        float* yp = Yout + (size_t)o * NT + tbase + 2 * tx;
        #pragma unroll
        for (int k = 0; k < 4; k++)
            *reinterpret_cast<u64*>(yp + 64 * k) = acc2[k][j];
    }

    // fused per-channel partial stats for this block's 256 samples
    #pragma unroll
    for (int j = 0; j < 8; j++) {
        float s = 0.f, q = 0.f;
        #pragma unroll
        for (int k = 0; k < 4; k++) {
            float lo, hi; upk2(acc2[k][j], lo, hi);
            s += lo; s += hi;
            q = fmaf(lo, lo, q);
            q = fmaf(hi, hi, q);
        }
        #pragma unroll
        for (int off = 16; off; off >>= 1) {
            s += __shfl_down_sync(0xffffffffu, s, off);
            q += __shfl_down_sync(0xffffffffu, q, off);
        }
        if (tx == 0) {
            const int o = obase + wp * 8 + j;
            g_psum[o * NSTILE + blockIdx.x] = s;
            g_psq [o * NSTILE + blockIdx.x] = q;
        }
    }
}

// ---------------- reduce partials -> BN scale/shift (layers 0,1) ----------
__global__ __launch_bounds__(256) void finalize_kernel(const float* __restrict__ g,
                                                       const float* __restrict__ beta)
{
    const int c = blockIdx.x;
    float s = 0.f, q = 0.f;
    for (int i = threadIdx.x; i < NSTILE; i += 256) {
        s += g_psum[c * NSTILE + i];
        q += g_psq [c * NSTILE + i];
    }
    __shared__ float rs[8], rq[8];
    #pragma unroll
    for (int off = 16; off; off >>= 1) {
        s += __shfl_down_sync(0xffffffffu, s, off);
        q += __shfl_down_sync(0xffffffffu, q, off);
    }
    int w = threadIdx.x >> 5;
    if ((threadIdx.x & 31) == 0) { rs[w] = s; rq[w] = q; }
    __syncthreads();
    if (threadIdx.x == 0) {
        float ts = 0.f, tq = 0.f;
        #pragma unroll
        for (int i = 0; i < 8; i++) { ts += rs[i]; tq += rq[i]; }
        float mu  = ts * (1.0f / NT);
        float var = tq * (1.0f / NT) - mu * mu;
        float rsq = rsqrtf(var + 1e-5f);
        float scv = g[c] * rsq;
        g_scale[c] = scv;
        g_shift[c] = fmaf(-mu, scv, beta[c]);
    }
}

// ---------------- layer-2 BN finalize + BN + ReLU + max over k ------------
// one block per (b, o); derives channel-o scale/shift from partials inline.
__global__ __launch_bounds__(256) void final_kernel(float* __restrict__ out2,
                                                    const float* __restrict__ g,
                                                    const float* __restrict__ beta)
{
    const int bo = blockIdx.x;
    const int b = bo >> 7;
    const int o = bo & 127;
    const int tid  = threadIdx.x;
    const int w    = tid >> 5;
    const int lane = tid & 31;

    __shared__ float rs[8], rq[8];
    __shared__ float s_sc, s_sh;
    {
        float s = 0.f, q = 0.f;
        for (int i = tid; i < NSTILE; i += 256) {
            s += g_psum[o * NSTILE + i];
            q += g_psq [o * NSTILE + i];
        }
        #pragma unroll
        for (int off = 16; off; off >>= 1) {
            s += __shfl_down_sync(0xffffffffu, s, off);
            q += __shfl_down_sync(0xffffffffu, q, off);
        }
        if (lane == 0) { rs[w] = s; rq[w] = q; }
        __syncthreads();
        if (tid == 0) {
            float ts = 0.f, tq = 0.f;
            #pragma unroll
            for (int i = 0; i < 8; i++) { ts += rs[i]; tq += rq[i]; }
            float mu  = ts * (1.0f / NT);
            float var = tq * (1.0f / NT) - mu * mu;
            float rsq = rsqrtf(var + 1e-5f);
            float scv = g[o] * rsq;
            s_sc = scv;
            s_sh = fmaf(-mu, scv, beta[o]);
        }
        __syncthreads();
    }
    const float scv = s_sc;
    const float shv = s_sh;

    const float* p = g_Y2 + (size_t)o * NT + (size_t)b * (NPOINT * NSAMPLE);
    for (int r = 0; r < 64; r++) {
        float v = p[tid + r * 256];
        v = fmaxf(0.f, fmaf(v, scv, shv));
        #pragma unroll
        for (int off = 16; off; off >>= 1)
            v = fmaxf(v, __shfl_down_sync(0xffffffffu, v, off));
        if (lane == 0)
            out2[(b * 128 + o) * NPOINT + (w + 8 * r)] = v;
    }
}

// ---------------- launch ----------------
extern "C" void kernel_launch(void* const* d_in, const int* in_sizes, int n_in,
                              void* d_out, int out_size)
{
    (void)in_sizes; (void)n_in; (void)out_size;
    const float* xyz    = (const float*)d_in[0];
    const float* points = (const float*)d_in[1];
    const float* W0 = (const float*)d_in[2];
    const float* b0 = (const float*)d_in[3];
    const float* g0 = (const float*)d_in[4];
    const float* be0= (const float*)d_in[5];
    const float* W1 = (const float*)d_in[6];
    const float* b1 = (const float*)d_in[7];
    const float* g1 = (const float*)d_in[8];
    const float* be1= (const float*)d_in[9];
    const float* W2 = (const float*)d_in[10];
    const float* b2 = (const float*)d_in[11];
    const float* g2 = (const float*)d_in[12];
    const float* be2= (const float*)d_in[13];

    float* out = (float*)d_out;

    fps_kernel<<<BATCH, 512>>>(xyz, out);
    ball_gather_kernel<<<(BATCH * NPOINT) / 8, 256>>>(xyz, points);

    layer_kernel<67, false, 0><<<dim3(NSTILE, 1), 256>>>(W0, b0);
    finalize_kernel<<<64, 256>>>(g0, be0);

    layer_kernel<64, true, 1><<<dim3(NSTILE, 1), 256>>>(W1, b1);
    finalize_kernel<<<64, 256>>>(g1, be1);

    layer_kernel<64, true, 2><<<dim3(NSTILE, 2), 256>>>(W2, b2);

    final_kernel<<<BATCH * 128, 256>>>(out + BATCH * 3 * NPOINT, g2, be2);
}